// round 7
// baseline (speedup 1.0000x reference)
#include <cuda_runtime.h>
#include <cuda_bf16.h>
#include <cstdint>

// Problem constants
#define B    32
#define SX   512
#define SM_  4096
#define D    256
#define TOPK 5
#define NCAND 16

#define NEG_INF (__int_as_float(0xff800000))

// int8 quantization: scale = 127/4 (clip at 4 sigma), fold (1/scale)^2 in epilogue
#define QSCALE 31.75f
#define INVS2  (1.0f / (QSCALE * QSCALE))

// GEMM tiling (s8: K steps of 32)
#define MT   128            // mem rows per CTA
#define NC   128            // query chunk
#define NCH  (SX / NC)      // 4 chunks
#define KSTEPS (D / 32)     // 8 k-steps of 32
#define SROW 272            // bytes per smem row (256 data + 16 pad)
#define NTHREADS 512

// Scratch (no allocations allowed)
__device__ float g_inv_na[B * SX];
__device__ float g_inv_nb[B * SM_];
__device__ float g_simmax[B * SM_];
__device__ int   g_cand[B * NCAND];
__device__ uint8_t g_xq[B * SX * D];    // 4 MB  s8
__device__ uint8_t g_mq[B * SM_ * D];   // 32 MB s8

// ---------------------------------------------------------------------------
// helpers
// ---------------------------------------------------------------------------
__device__ __forceinline__ uint32_t smem_u32(const void* p) {
    return (uint32_t)__cvta_generic_to_shared(p);
}

__device__ __forceinline__ int q8(float v) {
    int r = __float2int_rn(v * QSCALE);
    return max(-127, min(127, r));
}
__device__ __forceinline__ uint32_t pack_s8x4(float v0, float v1, float v2, float v3) {
    return (uint32_t)(q8(v0) & 0xFF) | ((uint32_t)(q8(v1) & 0xFF) << 8) |
           ((uint32_t)(q8(v2) & 0xFF) << 16) | ((uint32_t)(q8(v3) & 0xFF) << 24);
}

__device__ __forceinline__ void cp16(uint32_t dst, const void* src) {
    asm volatile("cp.async.cg.shared.global [%0], [%1], 16;" :: "r"(dst), "l"(src));
}
__device__ __forceinline__ void cp_commit() {
    asm volatile("cp.async.commit_group;" ::: "memory");
}
__device__ __forceinline__ void cp_wait(int n) {
    if (n == 0)      asm volatile("cp.async.wait_group 0;" ::: "memory");
    else if (n == 1) asm volatile("cp.async.wait_group 1;" ::: "memory");
    else if (n == 2) asm volatile("cp.async.wait_group 2;" ::: "memory");
    else             asm volatile("cp.async.wait_group 3;" ::: "memory");
}

__device__ __forceinline__ void ldsm_x4(uint32_t& r0, uint32_t& r1,
                                        uint32_t& r2, uint32_t& r3, uint32_t addr) {
    asm volatile("ldmatrix.sync.aligned.m8n8.x4.shared.b16 {%0,%1,%2,%3}, [%4];"
                 : "=r"(r0), "=r"(r1), "=r"(r2), "=r"(r3) : "r"(addr));
}

__device__ __forceinline__ void mma_s8(int& c0, int& c1, int& c2, int& c3,
                                       uint32_t a0, uint32_t a1, uint32_t a2, uint32_t a3,
                                       uint32_t b0, uint32_t b1) {
    asm volatile(
        "mma.sync.aligned.m16n8k32.row.col.s32.s8.s8.s32 "
        "{%0,%1,%2,%3}, {%4,%5,%6,%7}, {%8,%9}, {%0,%1,%2,%3};"
        : "+r"(c0), "+r"(c1), "+r"(c2), "+r"(c3)
        : "r"(a0), "r"(a1), "r"(a2), "r"(a3), "r"(b0), "r"(b1));
}

// ---------------------------------------------------------------------------
// 1) inverse L2 norm per row + s8 quantization (one warp per row of 256 floats)
// ---------------------------------------------------------------------------
__global__ void invnorm_kernel(const float* __restrict__ in, int rows, int which) {
    int gwarp = (blockIdx.x * blockDim.x + threadIdx.x) >> 5;
    int lane  = threadIdx.x & 31;
    if (gwarp >= rows) return;
    const float4* r = reinterpret_cast<const float4*>(in + (size_t)gwarp * D);
    float4 v0 = r[lane];
    float4 v1 = r[lane + 32];

    uint8_t* dst = (which ? g_mq : g_xq) + (size_t)gwarp * D;
    // contiguous: word L holds floats 4L..4L+3 ; word L+32 holds floats 128+4L..
    reinterpret_cast<uint32_t*>(dst)[lane]      = pack_s8x4(v0.x, v0.y, v0.z, v0.w);
    reinterpret_cast<uint32_t*>(dst)[lane + 32] = pack_s8x4(v1.x, v1.y, v1.z, v1.w);

    float s = v0.x * v0.x + v0.y * v0.y + v0.z * v0.z + v0.w * v0.w
            + v1.x * v1.x + v1.y * v1.y + v1.z * v1.z + v1.w * v1.w;
#pragma unroll
    for (int off = 16; off; off >>= 1)
        s += __shfl_xor_sync(0xffffffffu, s, off);
    if (lane == 0) {
        float iv = rsqrtf(s);
        if (which == 0) g_inv_na[gwarp] = iv;
        else            g_inv_nb[gwarp] = iv;
    }
}

// ---------------------------------------------------------------------------
// 2) tensor sim-max via mma.sync s8 (IMMA): CTA=(batch,128 mem rows);
//    512 threads, 4(m)x4(n) warp grid, warp tile 32x32; A + all 4 B chunks
//    resident in smem; exact s32 accumulation.
// ---------------------------------------------------------------------------
__device__ __forceinline__ void load_rows_async(uint32_t sdst, const uint8_t* gsrc,
                                                int rows, int tid) {
    for (int i = tid; i < rows * 16; i += NTHREADS) {
        const int r = i >> 4, c = i & 15;
        cp16(sdst + (uint32_t)(r * SROW + c * 16), gsrc + (size_t)r * D + c * 16);
    }
}

__global__ __launch_bounds__(NTHREADS, 1)
void simmax_mma_kernel() {
    extern __shared__ char smem[];
    const uint32_t sA = smem_u32(smem);
    const uint32_t sB = sA + MT * SROW;
    float* s_ina = reinterpret_cast<float*>(smem + MT * SROW + SX * SROW);
    float* red   = s_ina + SX;

    const int tid    = threadIdx.x;
    const int wid    = tid >> 5;
    const int lane   = tid & 31;
    const int b      = blockIdx.y;
    const int m0     = blockIdx.x * MT;
    const int warp_m = wid & 3;
    const int warp_n = wid >> 2;

    const uint8_t* Ag = g_mq + ((size_t)b * SM_ + m0) * D;
    const uint8_t* Xg = g_xq + (size_t)b * SX * D;

    // prologue: A + chunk0 (wait 3), chunk1 (2), chunk2 (1), chunk3 (0)
    load_rows_async(sA, Ag, MT, tid);
    load_rows_async(sB, Xg, NC, tid);
    cp_commit();
    load_rows_async(sB + NC * SROW, Xg + (size_t)NC * D, NC, tid);
    cp_commit();
    load_rows_async(sB + 2 * NC * SROW, Xg + (size_t)2 * NC * D, NC, tid);
    cp_commit();
    load_rows_async(sB + 3 * NC * SROW, Xg + (size_t)3 * NC * D, NC, tid);
    cp_commit();
#pragma unroll
    for (int i = tid; i < SX; i += NTHREADS)
        s_ina[i] = g_inv_na[b * SX + i] * INVS2;   // fold quant scale^2 here

    // ldmatrix lane addresses (1B elems; b16 view)
    const int g = lane >> 3, r8 = lane & 7;
    const uint32_t aA = sA +
        (uint32_t)((warp_m * 32 + (g & 1) * 8 + r8) * SROW + (g >> 1) * 16);
    const uint32_t aB0 = sB +
        (uint32_t)((warp_n * 32 + (g >> 1) * 8 + r8) * SROW + (g & 1) * 16);

    cp_wait(3);
    __syncthreads();

    float rmax[2][2];
#pragma unroll
    for (int i = 0; i < 2; ++i) rmax[i][0] = rmax[i][1] = NEG_INF;

    for (int c = 0; c < NCH; ++c) {
        const uint32_t aB = aB0 + (uint32_t)(c * NC * SROW);
        int acc[2][4][4];
#pragma unroll
        for (int mt = 0; mt < 2; ++mt)
#pragma unroll
            for (int nt = 0; nt < 4; ++nt)
#pragma unroll
                for (int q = 0; q < 4; ++q) acc[mt][nt][q] = 0;

#pragma unroll
        for (int ks = 0; ks < KSTEPS; ++ks) {
            const uint32_t koff = (uint32_t)(ks * 32);
            uint32_t a[2][4];
#pragma unroll
            for (int mt = 0; mt < 2; ++mt)
                ldsm_x4(a[mt][0], a[mt][1], a[mt][2], a[mt][3],
                        aA + (uint32_t)(mt * 16 * SROW) + koff);
            uint32_t bfr[4][2];
#pragma unroll
            for (int p = 0; p < 2; ++p) {
                uint32_t r0, r1, r2, r3;
                ldsm_x4(r0, r1, r2, r3, aB + (uint32_t)(p * 16 * SROW) + koff);
                bfr[p * 2][0]     = r0; bfr[p * 2][1]     = r1;
                bfr[p * 2 + 1][0] = r2; bfr[p * 2 + 1][1] = r3;
            }
#pragma unroll
            for (int mt = 0; mt < 2; ++mt)
#pragma unroll
                for (int nt = 0; nt < 4; ++nt)
                    mma_s8(acc[mt][nt][0], acc[mt][nt][1],
                           acc[mt][nt][2], acc[mt][nt][3],
                           a[mt][0], a[mt][1], a[mt][2], a[mt][3],
                           bfr[nt][0], bfr[nt][1]);
        }

        // fold chunk into running max (scale by 1/||x_s|| * invscale^2)
#pragma unroll
        for (int nt = 0; nt < 4; ++nt) {
            const int n0 = c * NC + warp_n * 32 + nt * 8 + (lane & 3) * 2;
            const float i0 = s_ina[n0], i1 = s_ina[n0 + 1];
#pragma unroll
            for (int mt = 0; mt < 2; ++mt) {
                rmax[mt][0] = fmaxf(rmax[mt][0],
                    fmaxf(__int2float_rn(acc[mt][nt][0]) * i0,
                          __int2float_rn(acc[mt][nt][1]) * i1));
                rmax[mt][1] = fmaxf(rmax[mt][1],
                    fmaxf(__int2float_rn(acc[mt][nt][2]) * i0,
                          __int2float_rn(acc[mt][nt][3]) * i1));
            }
        }

        if (c + 1 < NCH) cp_wait(3 - (c + 1));   // disjoint buffers; per-thread wait
    }

    // reduce over the 4 lanes (lane&3) sharing each m row
#pragma unroll
    for (int mt = 0; mt < 2; ++mt)
#pragma unroll
        for (int rh = 0; rh < 2; ++rh) {
            float v = rmax[mt][rh];
            v = fmaxf(v, __shfl_xor_sync(0xffffffffu, v, 1));
            v = fmaxf(v, __shfl_xor_sync(0xffffffffu, v, 2));
            rmax[mt][rh] = v;
        }
    __syncthreads();
    if ((lane & 3) == 0) {
#pragma unroll
        for (int mt = 0; mt < 2; ++mt)
#pragma unroll
            for (int rh = 0; rh < 2; ++rh) {
                const int m = warp_m * 32 + mt * 16 + rh * 8 + (lane >> 2);
                red[warp_n * MT + m] = rmax[mt][rh];
            }
    }
    __syncthreads();
    if (tid < MT) {
        float v = fmaxf(fmaxf(red[tid], red[MT + tid]),
                        fmaxf(red[2 * MT + tid], red[3 * MT + tid]));
        const int m = m0 + tid;
        g_simmax[b * SM_ + m] = v * g_inv_nb[b * SM_ + m];
    }
}

// ---------------------------------------------------------------------------
// 3) approx top-16 per batch: register-resident, warp-shuffle argmax rounds
// ---------------------------------------------------------------------------
__global__ __launch_bounds__(512)
void topk_approx_kernel() {
    __shared__ float swv[16];
    __shared__ int   swi[16];
    __shared__ int   s_win;

    const int b    = blockIdx.x;
    const int tid  = threadIdx.x;
    const int wid  = tid >> 5;
    const int lane = tid & 31;

    float e[8];
#pragma unroll
    for (int j = 0; j < 8; ++j) e[j] = g_simmax[b * SM_ + tid * 8 + j];

    for (int k = 0; k < NCAND; ++k) {
        float bv = e[0];
        int   bi = tid * 8;
#pragma unroll
        for (int j = 1; j < 8; ++j)
            if (e[j] > bv) { bv = e[j]; bi = tid * 8 + j; }
#pragma unroll
        for (int off = 16; off; off >>= 1) {
            float ov = __shfl_xor_sync(0xffffffffu, bv, off);
            int   oi = __shfl_xor_sync(0xffffffffu, bi, off);
            if (ov > bv || (ov == bv && oi < bi)) { bv = ov; bi = oi; }
        }
        if (lane == 0) { swv[wid] = bv; swi[wid] = bi; }
        __syncthreads();
        if (wid == 0) {
            float fv = (lane < 16) ? swv[lane] : NEG_INF;
            int   fi = (lane < 16) ? swi[lane] : 0x7fffffff;
#pragma unroll
            for (int off = 8; off; off >>= 1) {
                float ov = __shfl_xor_sync(0xffffffffu, fv, off);
                int   oi = __shfl_xor_sync(0xffffffffu, fi, off);
                if (ov > fv || (ov == fv && oi < fi)) { fv = ov; fi = oi; }
            }
            if (lane == 0) {
                s_win = fi;
                g_cand[b * NCAND + k] = fi;
            }
        }
        __syncthreads();
        const int w = s_win;
        if ((w >> 3) == tid) e[w & 7] = NEG_INF;
    }
}

// ---------------------------------------------------------------------------
// 4) exact fp32 re-rank of the 16 candidates, pick top-5, gather rows+indices
//    out layout (float32): 5 blocks of [B,D] then [B,TOPK] indices
// ---------------------------------------------------------------------------
__global__ __launch_bounds__(512)
void rerank_kernel(const float* __restrict__ x, const float* __restrict__ mem,
                   float* __restrict__ out) {
    __shared__ float s_m[NCAND][D];
    __shared__ float s_x[32][D + 1];
    __shared__ float s_score[NCAND];
    __shared__ int   s_sel[TOPK];

    const int b    = blockIdx.x;
    const int tid  = threadIdx.x;
    const int wid  = tid >> 5;     // 0..15 -> candidate id
    const int lane = tid & 31;

    for (int i = tid; i < NCAND * D; i += 512) {
        int c = i >> 8, d = i & 255;
        s_m[c][d] = mem[((size_t)b * SM_ + g_cand[b * NCAND + c]) * D + d];
    }

    float vmax = NEG_INF;
    for (int s0 = 0; s0 < SX; s0 += 32) {
        __syncthreads();
        for (int i = tid; i < 32 * D; i += 512) {
            int r = i >> 8, d = i & 255;
            s_x[r][d] = x[((size_t)b * SX + s0 + r) * D + d];
        }
        __syncthreads();
        float dot = 0.0f;
#pragma unroll 8
        for (int d = 0; d < D; ++d)
            dot = fmaf(s_x[lane][d], s_m[wid][d], dot);
        vmax = fmaxf(vmax, dot * g_inv_na[b * SX + s0 + lane]);
    }
#pragma unroll
    for (int off = 16; off; off >>= 1)
        vmax = fmaxf(vmax, __shfl_xor_sync(0xffffffffu, vmax, off));
    if (lane == 0)
        s_score[wid] = vmax * g_inv_nb[b * SM_ + g_cand[b * NCAND + wid]];
    __syncthreads();

    if (tid == 0) {
        float sc[NCAND];
        int   ix[NCAND];
        for (int i = 0; i < NCAND; ++i) {
            sc[i] = s_score[i];
            ix[i] = g_cand[b * NCAND + i];
        }
        for (int k = 0; k < TOPK; ++k) {
            int best = k;
            for (int j = k + 1; j < NCAND; ++j)
                if (sc[j] > sc[best] || (sc[j] == sc[best] && ix[j] < ix[best])) best = j;
            float ts = sc[k]; sc[k] = sc[best]; sc[best] = ts;
            int   ti = ix[k]; ix[k] = ix[best]; ix[best] = ti;
            s_sel[k] = ix[k];
        }
    }
    __syncthreads();

    if (tid < 256) {
        for (int k = 0; k < TOPK; ++k)
            out[(size_t)k * B * D + (size_t)b * D + tid] =
                mem[((size_t)b * SM_ + s_sel[k]) * D + tid];
    }
    if (tid < TOPK)
        out[(size_t)TOPK * B * D + b * TOPK + tid] = (float)s_sel[tid];
}

// ---------------------------------------------------------------------------
extern "C" void kernel_launch(void* const* d_in, const int* in_sizes, int n_in,
                              void* d_out, int out_size) {
    const float* x   = (const float*)d_in[0];   // [B, SX, D]
    const float* mem = (const float*)d_in[1];   // [B, SM, D]
    float* out = (float*)d_out;
    (void)in_sizes; (void)n_in; (void)out_size;

    invnorm_kernel<<<(B * SX) / 8, 256>>>(x, B * SX, 0);
    invnorm_kernel<<<(B * SM_) / 8, 256>>>(mem, B * SM_, 1);

    const int smem_bytes = (MT + SX) * SROW + (SX + 4 * MT) * 4;   // 178,176 B
    static bool attr_set = false;   // idempotent attribute, not work caching
    if (!attr_set) {
        cudaFuncSetAttribute(simmax_mma_kernel,
                             cudaFuncAttributeMaxDynamicSharedMemorySize, smem_bytes);
        attr_set = true;
    }
    dim3 grid(SM_ / MT, B);
    simmax_mma_kernel<<<grid, NTHREADS, smem_bytes>>>();

    topk_approx_kernel<<<B, 512>>>();
    rerank_kernel<<<B, 512>>>(x, mem, out);
}

// round 8
// speedup vs baseline: 1.5427x; 1.5427x over previous
#include <cuda_runtime.h>
#include <cuda_fp16.h>
#include <cstdint>

// Problem constants
#define B    32
#define SX   512
#define SM_  4096
#define D    256
#define TOPK 5
#define NCAND 16

#define NEG_INF (__int_as_float(0xff800000))

// GEMM tiling
#define MT   128          // mem rows per CTA
#define NC   128          // query chunk
#define NCH  (SX / NC)    // 4 chunks
#define KSTEPS (D / 16)   // 16 k-steps of 16
#define STRIDE 264        // f16 elems per smem row (528B: 16B aligned, 4-bank stagger)
#define NTHREADS 512

// Scratch (no allocations allowed)
__device__ float g_inv_na[B * SX];
__device__ float g_inv_nb[B * SM_];
__device__ float g_simmax[B * SM_];
__device__ int   g_cand[B * NCAND];
__device__ __half g_xh[B * SX * D];    // 8 MB
__device__ __half g_mh[B * SM_ * D];   // 64 MB

// ---------------------------------------------------------------------------
// helpers
// ---------------------------------------------------------------------------
__device__ __forceinline__ uint32_t smem_u32(const void* p) {
    return (uint32_t)__cvta_generic_to_shared(p);
}

__device__ __forceinline__ uint32_t pack_h2(float a, float b) {
    __half2 h = __float22half2_rn(make_float2(a, b));
    return *reinterpret_cast<uint32_t*>(&h);
}

__device__ __forceinline__ void cp16(uint32_t dst, const void* src) {
    asm volatile("cp.async.cg.shared.global [%0], [%1], 16;" :: "r"(dst), "l"(src));
}
__device__ __forceinline__ void cp_commit() {
    asm volatile("cp.async.commit_group;" ::: "memory");
}
__device__ __forceinline__ void cp_wait0() {
    asm volatile("cp.async.wait_group 0;" ::: "memory");
}

__device__ __forceinline__ void ldsm_x4(uint32_t& r0, uint32_t& r1,
                                        uint32_t& r2, uint32_t& r3, uint32_t addr) {
    asm volatile("ldmatrix.sync.aligned.m8n8.x4.shared.b16 {%0,%1,%2,%3}, [%4];"
                 : "=r"(r0), "=r"(r1), "=r"(r2), "=r"(r3) : "r"(addr));
}

// f16 accumulate: D/C are 2 regs, each holding 2 halves
__device__ __forceinline__ void mma_f16acc(uint32_t& d0, uint32_t& d1,
                                           uint32_t a0, uint32_t a1, uint32_t a2, uint32_t a3,
                                           uint32_t b0, uint32_t b1) {
    asm volatile(
        "mma.sync.aligned.m16n8k16.row.col.f16.f16.f16.f16 "
        "{%0,%1}, {%2,%3,%4,%5}, {%6,%7}, {%0,%1};"
        : "+r"(d0), "+r"(d1)
        : "r"(a0), "r"(a1), "r"(a2), "r"(a3), "r"(b0), "r"(b1));
}

// ---------------------------------------------------------------------------
// 1) inverse L2 norm per row + f16 conversion (one warp per row of 256 floats)
// ---------------------------------------------------------------------------
__global__ void invnorm_kernel(const float* __restrict__ in, int rows, int which) {
    int gwarp = (blockIdx.x * blockDim.x + threadIdx.x) >> 5;
    int lane  = threadIdx.x & 31;
    if (gwarp >= rows) return;
    const float4* r = reinterpret_cast<const float4*>(in + (size_t)gwarp * D);
    float4 v0 = r[lane];
    float4 v1 = r[lane + 32];

    __half* dst = (which ? g_mh : g_xh) + (size_t)gwarp * D;
    // contiguous: uint2 at elem-offset L covers halves 8L..8L+7 -> needs floats 8L..
    // use two uint2 stores at the correct offsets instead:
    uint2 wa = make_uint2(pack_h2(v0.x, v0.y), pack_h2(v0.z, v0.w)); // floats 4L..4L+3
    uint2 wb = make_uint2(pack_h2(v1.x, v1.y), pack_h2(v1.z, v1.w)); // floats 128+4L..
    reinterpret_cast<uint64_t*>(dst)[lane]      = *reinterpret_cast<uint64_t*>(&wa) ;
    reinterpret_cast<uint64_t*>(dst)[lane + 32] = *reinterpret_cast<uint64_t*>(&wb) ;
    // note: uint64 slot L = halves 4L..4L+3 (8 bytes) -> floats 4L..4L+3. correct.

    float s = v0.x * v0.x + v0.y * v0.y + v0.z * v0.z + v0.w * v0.w
            + v1.x * v1.x + v1.y * v1.y + v1.z * v1.z + v1.w * v1.w;
#pragma unroll
    for (int off = 16; off; off >>= 1)
        s += __shfl_xor_sync(0xffffffffu, s, off);
    if (lane == 0) {
        float iv = rsqrtf(s);
        if (which == 0) g_inv_na[gwarp] = iv;
        else            g_inv_nb[gwarp] = iv;
    }
}

// ---------------------------------------------------------------------------
// 2) tensor sim-max via mma.sync f16 (f16 acc), 512 threads, 4x4 warp grid,
//    warp tile 32x32, double-buffered cp.async B chunks.
// ---------------------------------------------------------------------------
__device__ __forceinline__ void load_tile_async(uint32_t sdst,
                                                const __half* gsrc, int tid) {
    // 128 rows x 512B, padded stride 528B; 16B per cp.async
#pragma unroll
    for (int i = tid; i < MT * 32; i += NTHREADS) {
        const int r = i >> 5, c = i & 31;
        cp16(sdst + (uint32_t)(r * (STRIDE * 2) + c * 16), gsrc + (size_t)r * D + c * 8);
    }
}

__global__ __launch_bounds__(NTHREADS, 1)
void simmax_mma_kernel() {
    extern __shared__ char smem[];
    __half* sA  = reinterpret_cast<__half*>(smem);   // [128][STRIDE]
    __half* sB0 = sA + MT * STRIDE;
    __half* sB1 = sB0 + NC * STRIDE;
    float* s_ina = reinterpret_cast<float*>(sB1 + NC * STRIDE);    // [512]
    float* red   = s_ina + SX;                                     // [4*128]

    const int tid    = threadIdx.x;
    const int wid    = tid >> 5;
    const int lane   = tid & 31;
    const int b      = blockIdx.y;
    const int m0     = blockIdx.x * MT;
    const int warp_m = wid & 3;       // m block of 32
    const int warp_n = wid >> 2;      // n block of 32

    const __half* Ag = g_mh + ((size_t)b * SM_ + m0) * D;
    const __half* Xg = g_xh + (size_t)b * SX * D;

    load_tile_async(smem_u32(sA), Ag, tid);
    cp_commit();
    load_tile_async(smem_u32(sB0), Xg, tid);
    cp_commit();
#pragma unroll
    for (int i = tid; i < SX; i += NTHREADS) s_ina[i] = g_inv_na[b * SX + i];
    cp_wait0();
    __syncthreads();

    // ldmatrix lane addresses
    const int g = lane >> 3, r8 = lane & 7;
    const uint32_t aA = smem_u32(sA) +
        (uint32_t)(((warp_m * 32 + (g & 1) * 8 + r8) * STRIDE + (g >> 1) * 8) * 2);
    const uint32_t aBoff =
        (uint32_t)(((warp_n * 32 + (g >> 1) * 8 + r8) * STRIDE + (g & 1) * 8) * 2);
    const uint32_t aBbuf[2] = { smem_u32(sB0) + aBoff, smem_u32(sB1) + aBoff };
    const uint32_t sBbuf[2] = { smem_u32(sB0), smem_u32(sB1) };

    float rmax[2][2];
#pragma unroll
    for (int i = 0; i < 2; ++i) rmax[i][0] = rmax[i][1] = NEG_INF;

    for (int c = 0; c < NCH; ++c) {
        if (c + 1 < NCH) {
            load_tile_async(sBbuf[(c + 1) & 1], Xg + (size_t)(c + 1) * NC * D, tid);
            cp_commit();
        }

        const uint32_t aB = aBbuf[c & 1];
        uint32_t acc[2][4][2];   // f16x2 accumulators
#pragma unroll
        for (int mt = 0; mt < 2; ++mt)
#pragma unroll
            for (int nt = 0; nt < 4; ++nt)
                acc[mt][nt][0] = acc[mt][nt][1] = 0u;

#pragma unroll 4
        for (int ks = 0; ks < KSTEPS; ++ks) {
            const uint32_t koff = (uint32_t)(ks * 16 * 2);
            uint32_t a[2][4];
#pragma unroll
            for (int mt = 0; mt < 2; ++mt)
                ldsm_x4(a[mt][0], a[mt][1], a[mt][2], a[mt][3],
                        aA + (uint32_t)(mt * 16 * STRIDE * 2) + koff);
            uint32_t bfr[4][2];
#pragma unroll
            for (int p = 0; p < 2; ++p) {
                uint32_t r0, r1, r2, r3;
                ldsm_x4(r0, r1, r2, r3,
                        aB + (uint32_t)(p * 16 * STRIDE * 2) + koff);
                bfr[p * 2][0]     = r0; bfr[p * 2][1]     = r1;
                bfr[p * 2 + 1][0] = r2; bfr[p * 2 + 1][1] = r3;
            }
#pragma unroll
            for (int mt = 0; mt < 2; ++mt)
#pragma unroll
                for (int nt = 0; nt < 4; ++nt)
                    mma_f16acc(acc[mt][nt][0], acc[mt][nt][1],
                               a[mt][0], a[mt][1], a[mt][2], a[mt][3],
                               bfr[nt][0], bfr[nt][1]);
        }

        // fold chunk into running max (unpack f16 pairs, scale by 1/||x_s||)
#pragma unroll
        for (int nt = 0; nt < 4; ++nt) {
            const int n0 = c * NC + warp_n * 32 + nt * 8 + (lane & 3) * 2;
            const float i0 = s_ina[n0], i1 = s_ina[n0 + 1];
#pragma unroll
            for (int mt = 0; mt < 2; ++mt) {
                float2 p0 = __half22float2(
                    *reinterpret_cast<__half2*>(&acc[mt][nt][0]));  // c0,c1 (row r)
                float2 p1 = __half22float2(
                    *reinterpret_cast<__half2*>(&acc[mt][nt][1]));  // c2,c3 (row r+8)
                rmax[mt][0] = fmaxf(rmax[mt][0], fmaxf(p0.x * i0, p0.y * i1));
                rmax[mt][1] = fmaxf(rmax[mt][1], fmaxf(p1.x * i0, p1.y * i1));
            }
        }

        if (c + 1 < NCH) {
            cp_wait0();
            __syncthreads();
        }
    }

    // reduce over the 4 lanes (lane&3) sharing each m row
#pragma unroll
    for (int mt = 0; mt < 2; ++mt)
#pragma unroll
        for (int rh = 0; rh < 2; ++rh) {
            float v = rmax[mt][rh];
            v = fmaxf(v, __shfl_xor_sync(0xffffffffu, v, 1));
            v = fmaxf(v, __shfl_xor_sync(0xffffffffu, v, 2));
            rmax[mt][rh] = v;
        }
    __syncthreads();
    if ((lane & 3) == 0) {
#pragma unroll
        for (int mt = 0; mt < 2; ++mt)
#pragma unroll
            for (int rh = 0; rh < 2; ++rh) {
                const int m = warp_m * 32 + mt * 16 + rh * 8 + (lane >> 2);
                red[warp_n * MT + m] = rmax[mt][rh];
            }
    }
    __syncthreads();
    if (tid < MT) {
        float v = fmaxf(fmaxf(red[tid], red[MT + tid]),
                        fmaxf(red[2 * MT + tid], red[3 * MT + tid]));
        const int m = m0 + tid;
        g_simmax[b * SM_ + m] = v * g_inv_nb[b * SM_ + m];
    }
}

// ---------------------------------------------------------------------------
// 3) approx top-16 per batch: register-resident, warp-shuffle argmax rounds
// ---------------------------------------------------------------------------
__global__ __launch_bounds__(512)
void topk_approx_kernel() {
    __shared__ float swv[16];
    __shared__ int   swi[16];
    __shared__ int   s_win;

    const int b    = blockIdx.x;
    const int tid  = threadIdx.x;
    const int wid  = tid >> 5;
    const int lane = tid & 31;

    float e[8];
#pragma unroll
    for (int j = 0; j < 8; ++j) e[j] = g_simmax[b * SM_ + tid * 8 + j];

    for (int k = 0; k < NCAND; ++k) {
        float bv = e[0];
        int   bi = tid * 8;
#pragma unroll
        for (int j = 1; j < 8; ++j)
            if (e[j] > bv) { bv = e[j]; bi = tid * 8 + j; }
#pragma unroll
        for (int off = 16; off; off >>= 1) {
            float ov = __shfl_xor_sync(0xffffffffu, bv, off);
            int   oi = __shfl_xor_sync(0xffffffffu, bi, off);
            if (ov > bv || (ov == bv && oi < bi)) { bv = ov; bi = oi; }
        }
        if (lane == 0) { swv[wid] = bv; swi[wid] = bi; }
        __syncthreads();
        if (wid == 0) {
            float fv = (lane < 16) ? swv[lane] : NEG_INF;
            int   fi = (lane < 16) ? swi[lane] : 0x7fffffff;
#pragma unroll
            for (int off = 8; off; off >>= 1) {
                float ov = __shfl_xor_sync(0xffffffffu, fv, off);
                int   oi = __shfl_xor_sync(0xffffffffu, fi, off);
                if (ov > fv || (ov == fv && oi < fi)) { fv = ov; fi = oi; }
            }
            if (lane == 0) {
                s_win = fi;
                g_cand[b * NCAND + k] = fi;
            }
        }
        __syncthreads();
        const int w = s_win;
        if ((w >> 3) == tid) e[w & 7] = NEG_INF;
    }
}

// ---------------------------------------------------------------------------
// 4) exact fp32 re-rank of the 16 candidates, pick top-5, gather rows+indices
//    out layout (float32): 5 blocks of [B,D] then [B,TOPK] indices
// ---------------------------------------------------------------------------
__global__ __launch_bounds__(512)
void rerank_kernel(const float* __restrict__ x, const float* __restrict__ mem,
                   float* __restrict__ out) {
    __shared__ float s_m[NCAND][D];
    __shared__ float s_x[32][D + 1];
    __shared__ float s_score[NCAND];
    __shared__ int   s_sel[TOPK];

    const int b    = blockIdx.x;
    const int tid  = threadIdx.x;
    const int wid  = tid >> 5;     // 0..15 -> candidate id
    const int lane = tid & 31;

    for (int i = tid; i < NCAND * D; i += 512) {
        int c = i >> 8, d = i & 255;
        s_m[c][d] = mem[((size_t)b * SM_ + g_cand[b * NCAND + c]) * D + d];
    }

    float vmax = NEG_INF;
    for (int s0 = 0; s0 < SX; s0 += 32) {
        __syncthreads();
        for (int i = tid; i < 32 * D; i += 512) {
            int r = i >> 8, d = i & 255;
            s_x[r][d] = x[((size_t)b * SX + s0 + r) * D + d];
        }
        __syncthreads();
        float dot = 0.0f;
#pragma unroll 8
        for (int d = 0; d < D; ++d)
            dot = fmaf(s_x[lane][d], s_m[wid][d], dot);
        vmax = fmaxf(vmax, dot * g_inv_na[b * SX + s0 + lane]);
    }
#pragma unroll
    for (int off = 16; off; off >>= 1)
        vmax = fmaxf(vmax, __shfl_xor_sync(0xffffffffu, vmax, off));
    if (lane == 0)
        s_score[wid] = vmax * g_inv_nb[b * SM_ + g_cand[b * NCAND + wid]];
    __syncthreads();

    if (tid == 0) {
        float sc[NCAND];
        int   ix[NCAND];
        for (int i = 0; i < NCAND; ++i) {
            sc[i] = s_score[i];
            ix[i] = g_cand[b * NCAND + i];
        }
        for (int k = 0; k < TOPK; ++k) {
            int best = k;
            for (int j = k + 1; j < NCAND; ++j)
                if (sc[j] > sc[best] || (sc[j] == sc[best] && ix[j] < ix[best])) best = j;
            float ts = sc[k]; sc[k] = sc[best]; sc[best] = ts;
            int   ti = ix[k]; ix[k] = ix[best]; ix[best] = ti;
            s_sel[k] = ix[k];
        }
    }
    __syncthreads();

    if (tid < 256) {
        for (int k = 0; k < TOPK; ++k)
            out[(size_t)k * B * D + (size_t)b * D + tid] =
                mem[((size_t)b * SM_ + s_sel[k]) * D + tid];
    }
    if (tid < TOPK)
        out[(size_t)TOPK * B * D + b * TOPK + tid] = (float)s_sel[tid];
}

// ---------------------------------------------------------------------------
extern "C" void kernel_launch(void* const* d_in, const int* in_sizes, int n_in,
                              void* d_out, int out_size) {
    const float* x   = (const float*)d_in[0];   // [B, SX, D]
    const float* mem = (const float*)d_in[1];   // [B, SM, D]
    float* out = (float*)d_out;
    (void)in_sizes; (void)n_in; (void)out_size;

    invnorm_kernel<<<(B * SX) / 8, 256>>>(x, B * SX, 0);
    invnorm_kernel<<<(B * SM_) / 8, 256>>>(mem, B * SM_, 1);

    const int smem_bytes = (MT * STRIDE + 2 * NC * STRIDE) * 2 + (SX + 4 * MT) * 4; // ~207 KB
    static bool attr_set = false;   // idempotent attribute, not work caching
    if (!attr_set) {
        cudaFuncSetAttribute(simmax_mma_kernel,
                             cudaFuncAttributeMaxDynamicSharedMemorySize, smem_bytes);
        attr_set = true;
    }
    dim3 grid(SM_ / MT, B);
    simmax_mma_kernel<<<grid, NTHREADS, smem_bytes>>>();

    topk_approx_kernel<<<B, 512>>>();
    rerank_kernel<<<B, 512>>>(x, mem, out);
}

// round 10
// speedup vs baseline: 1.6501x; 1.0696x over previous
#include <cuda_runtime.h>
#include <cuda_bf16.h>
#include <cstdint>

// Problem constants
#define B    32
#define SX   512
#define SM_  4096
#define D    256
#define TOPK 5
#define NCAND 16

#define NEG_INF (__int_as_float(0xff800000))

// GEMM tiling
#define MT   128          // mem rows per CTA
#define NC   128          // query chunk
#define NCH  (SX / NC)    // 4 chunks
#define KSTEPS (D / 16)   // 16 k-steps of 16
#define STRIDE 264        // bf16 elems per smem row (528B: 16B aligned, 4-bank stagger)
#define NTHREADS 512

// Scratch (no allocations allowed)
__device__ float g_inv_na[B * SX];
__device__ float g_simmax[B * SM_];
__device__ int   g_cand[B * NCAND];
__device__ __nv_bfloat16 g_xbf[B * SX * D];    // 8 MB

// ---------------------------------------------------------------------------
// helpers
// ---------------------------------------------------------------------------
__device__ __forceinline__ uint32_t smem_u32(const void* p) {
    return (uint32_t)__cvta_generic_to_shared(p);
}

__device__ __forceinline__ uint32_t pack_bf2(float a, float b) {
    __nv_bfloat162 h = __float22bfloat162_rn(make_float2(a, b));
    return *reinterpret_cast<uint32_t*>(&h);
}

__device__ __forceinline__ void cp16(uint32_t dst, const void* src) {
    asm volatile("cp.async.cg.shared.global [%0], [%1], 16;" :: "r"(dst), "l"(src));
}
__device__ __forceinline__ void cp_commit() {
    asm volatile("cp.async.commit_group;" ::: "memory");
}
__device__ __forceinline__ void cp_wait0() {
    asm volatile("cp.async.wait_group 0;" ::: "memory");
}

__device__ __forceinline__ void ldsm_x4(uint32_t& r0, uint32_t& r1,
                                        uint32_t& r2, uint32_t& r3, uint32_t addr) {
    asm volatile("ldmatrix.sync.aligned.m8n8.x4.shared.b16 {%0,%1,%2,%3}, [%4];"
                 : "=r"(r0), "=r"(r1), "=r"(r2), "=r"(r3) : "r"(addr));
}

__device__ __forceinline__ void mma_bf16(float& c0, float& c1, float& c2, float& c3,
                                         uint32_t a0, uint32_t a1, uint32_t a2, uint32_t a3,
                                         uint32_t b0, uint32_t b1) {
    asm volatile(
        "mma.sync.aligned.m16n8k16.row.col.f32.bf16.bf16.f32 "
        "{%0,%1,%2,%3}, {%4,%5,%6,%7}, {%8,%9}, {%0,%1,%2,%3};"
        : "+f"(c0), "+f"(c1), "+f"(c2), "+f"(c3)
        : "r"(a0), "r"(a1), "r"(a2), "r"(a3), "r"(b0), "r"(b1));
}

// ---------------------------------------------------------------------------
// 1) x only: inverse L2 norm per row + bf16 conversion (one warp per row)
// ---------------------------------------------------------------------------
__global__ void invnorm_x_kernel(const float* __restrict__ in) {
    int gwarp = (blockIdx.x * blockDim.x + threadIdx.x) >> 5;
    int lane  = threadIdx.x & 31;
    if (gwarp >= B * SX) return;
    const float4* r = reinterpret_cast<const float4*>(in + (size_t)gwarp * D);
    float4 v0 = r[lane];
    float4 v1 = r[lane + 32];

    __nv_bfloat16* dst = g_xbf + (size_t)gwarp * D;
    // u64 slot L holds halves 4L..4L+3 -> floats 4L..4L+3 ; slot L+32 -> 128+4L..
    uint2 wa = make_uint2(pack_bf2(v0.x, v0.y), pack_bf2(v0.z, v0.w));
    uint2 wb = make_uint2(pack_bf2(v1.x, v1.y), pack_bf2(v1.z, v1.w));
    reinterpret_cast<uint64_t*>(dst)[lane]      = *reinterpret_cast<uint64_t*>(&wa);
    reinterpret_cast<uint64_t*>(dst)[lane + 32] = *reinterpret_cast<uint64_t*>(&wb);

    float s = v0.x * v0.x + v0.y * v0.y + v0.z * v0.z + v0.w * v0.w
            + v1.x * v1.x + v1.y * v1.y + v1.z * v1.z + v1.w * v1.w;
#pragma unroll
    for (int off = 16; off; off >>= 1)
        s += __shfl_xor_sync(0xffffffffu, s, off);
    if (lane == 0) g_inv_na[gwarp] = rsqrtf(s);
}

// ---------------------------------------------------------------------------
// 2) fused tensor sim-max: A loaded fp32->bf16 + per-row norms computed
//    in-kernel; mma.sync bf16; 512 threads, 4x4 warp grid, warp tile 32x32;
//    double-buffered cp.async B chunks (pre-converted bf16 x).
// ---------------------------------------------------------------------------
__device__ __forceinline__ void load_tile_async(uint32_t sdst,
                                                const __nv_bfloat16* gsrc, int tid) {
#pragma unroll
    for (int i = tid; i < MT * 32; i += NTHREADS) {
        const int r = i >> 5, c = i & 31;
        cp16(sdst + (uint32_t)(r * (STRIDE * 2) + c * 16), gsrc + (size_t)r * D + c * 8);
    }
}

__global__ __launch_bounds__(NTHREADS, 1)
void simmax_mma_kernel(const float* __restrict__ mem) {
    extern __shared__ char smem[];
    __nv_bfloat16* sA  = reinterpret_cast<__nv_bfloat16*>(smem);   // [128][STRIDE]
    __nv_bfloat16* sB0 = sA + MT * STRIDE;
    __nv_bfloat16* sB1 = sB0 + NC * STRIDE;
    float* s_ina = reinterpret_cast<float*>(sB1 + NC * STRIDE);    // [512]
    float* s_inb = s_ina + SX;                                     // [128]
    float* red   = s_inb + MT;                                     // [4*128]

    const int tid    = threadIdx.x;
    const int wid    = tid >> 5;
    const int lane   = tid & 31;
    const int b      = blockIdx.y;
    const int m0     = blockIdx.x * MT;
    const int warp_m = wid & 3;       // m block of 32
    const int warp_n = wid >> 2;      // n block of 32

    const float* Ag = mem + ((size_t)b * SM_ + m0) * D;
    const __nv_bfloat16* Xg = g_xbf + (size_t)b * SX * D;

    // ---- prologue ----
    // B chunk 0 in flight first so it overlaps the fp32 A load below
    load_tile_async(smem_u32(sB0), Xg, tid);
    cp_commit();

    // A tile: fp32 LDG (coalesced) -> bf16 STS.
    // 128 rows x 64 float4 per row = 8192 float4 ops -> 16 iterations of 512.
#pragma unroll
    for (int j = 0; j < 16; ++j) {
        const int idx = j * NTHREADS + tid;      // [0, 8192)
        const int r = idx >> 6, q = idx & 63;    // 64 float4 per row
        float4 v = reinterpret_cast<const float4*>(Ag)[(size_t)r * 64 + q];
        uint2 w = make_uint2(pack_bf2(v.x, v.y), pack_bf2(v.z, v.w));
        *reinterpret_cast<uint2*>(
            reinterpret_cast<char*>(sA) + r * (STRIDE * 2) + q * 8) = w;
    }
#pragma unroll
    for (int i = tid; i < SX; i += NTHREADS) s_ina[i] = g_inv_na[b * SX + i];
    __syncthreads();   // sA visible

    // per-row inv norms from the (bf16) A tile: 4 threads per row
    {
        const int r  = tid >> 2;
        const int q0 = (tid & 3) * 64;   // quarter of the row (elements)
        const __nv_bfloat16* row = sA + r * STRIDE + q0;
        float s = 0.0f;
#pragma unroll
        for (int k = 0; k < 32; ++k) {
            float2 p = __bfloat1622float2(
                *reinterpret_cast<const __nv_bfloat162*>(row + 2 * k));
            s = fmaf(p.x, p.x, fmaf(p.y, p.y, s));
        }
        s += __shfl_xor_sync(0xffffffffu, s, 1);
        s += __shfl_xor_sync(0xffffffffu, s, 2);
        if ((tid & 3) == 0) s_inb[r] = rsqrtf(s);
    }
    cp_wait0();        // B chunk 0 landed
    __syncthreads();

    // ldmatrix lane addresses
    const int g = lane >> 3, r8 = lane & 7;
    const uint32_t aA = smem_u32(sA) +
        (uint32_t)(((warp_m * 32 + (g & 1) * 8 + r8) * STRIDE + (g >> 1) * 8) * 2);
    const uint32_t aBoff =
        (uint32_t)(((warp_n * 32 + (g >> 1) * 8 + r8) * STRIDE + (g & 1) * 8) * 2);
    const uint32_t aBbuf[2] = { smem_u32(sB0) + aBoff, smem_u32(sB1) + aBoff };
    const uint32_t sBbuf[2] = { smem_u32(sB0), smem_u32(sB1) };

    float rmax[2][2];
#pragma unroll
    for (int i = 0; i < 2; ++i) rmax[i][0] = rmax[i][1] = NEG_INF;

    for (int c = 0; c < NCH; ++c) {
        if (c + 1 < NCH) {
            load_tile_async(sBbuf[(c + 1) & 1], Xg + (size_t)(c + 1) * NC * D, tid);
            cp_commit();
        }

        const uint32_t aB = aBbuf[c & 1];
        float acc[2][4][4];
#pragma unroll
        for (int mt = 0; mt < 2; ++mt)
#pragma unroll
            for (int nt = 0; nt < 4; ++nt)
#pragma unroll
                for (int q = 0; q < 4; ++q) acc[mt][nt][q] = 0.0f;

#pragma unroll 4
        for (int ks = 0; ks < KSTEPS; ++ks) {
            const uint32_t koff = (uint32_t)(ks * 16 * 2);
            uint32_t a[2][4];
#pragma unroll
            for (int mt = 0; mt < 2; ++mt)
                ldsm_x4(a[mt][0], a[mt][1], a[mt][2], a[mt][3],
                        aA + (uint32_t)(mt * 16 * STRIDE * 2) + koff);
            uint32_t bfr[4][2];
#pragma unroll
            for (int p = 0; p < 2; ++p) {
                uint32_t r0, r1, r2, r3;
                ldsm_x4(r0, r1, r2, r3,
                        aB + (uint32_t)(p * 16 * STRIDE * 2) + koff);
                bfr[p * 2][0]     = r0; bfr[p * 2][1]     = r1;
                bfr[p * 2 + 1][0] = r2; bfr[p * 2 + 1][1] = r3;
            }
#pragma unroll
            for (int mt = 0; mt < 2; ++mt)
#pragma unroll
                for (int nt = 0; nt < 4; ++nt)
                    mma_bf16(acc[mt][nt][0], acc[mt][nt][1],
                             acc[mt][nt][2], acc[mt][nt][3],
                             a[mt][0], a[mt][1], a[mt][2], a[mt][3],
                             bfr[nt][0], bfr[nt][1]);
        }

        // fold chunk into running max (scale by 1/||x_s||)
#pragma unroll
        for (int nt = 0; nt < 4; ++nt) {
            const int n0 = c * NC + warp_n * 32 + nt * 8 + (lane & 3) * 2;
            const float i0 = s_ina[n0], i1 = s_ina[n0 + 1];
#pragma unroll
            for (int mt = 0; mt < 2; ++mt) {
                rmax[mt][0] = fmaxf(rmax[mt][0],
                                    fmaxf(acc[mt][nt][0] * i0, acc[mt][nt][1] * i1));
                rmax[mt][1] = fmaxf(rmax[mt][1],
                                    fmaxf(acc[mt][nt][2] * i0, acc[mt][nt][3] * i1));
            }
        }

        if (c + 1 < NCH) {
            cp_wait0();
            __syncthreads();
        }
    }

    // reduce over the 4 lanes (lane&3) sharing each m row
#pragma unroll
    for (int mt = 0; mt < 2; ++mt)
#pragma unroll
        for (int rh = 0; rh < 2; ++rh) {
            float v = rmax[mt][rh];
            v = fmaxf(v, __shfl_xor_sync(0xffffffffu, v, 1));
            v = fmaxf(v, __shfl_xor_sync(0xffffffffu, v, 2));
            rmax[mt][rh] = v;
        }
    __syncthreads();
    if ((lane & 3) == 0) {
#pragma unroll
        for (int mt = 0; mt < 2; ++mt)
#pragma unroll
            for (int rh = 0; rh < 2; ++rh) {
                const int m = warp_m * 32 + mt * 16 + rh * 8 + (lane >> 2);
                red[warp_n * MT + m] = rmax[mt][rh];
            }
    }
    __syncthreads();
    if (tid < MT) {
        float v = fmaxf(fmaxf(red[tid], red[MT + tid]),
                        fmaxf(red[2 * MT + tid], red[3 * MT + tid]));
        g_simmax[b * SM_ + m0 + tid] = v * s_inb[tid];
    }
}

// ---------------------------------------------------------------------------
// 3) approx top-16 per batch: register-resident, warp-shuffle argmax rounds
// ---------------------------------------------------------------------------
__global__ __launch_bounds__(512)
void topk_approx_kernel() {
    __shared__ float swv[16];
    __shared__ int   swi[16];
    __shared__ int   s_win;

    const int b    = blockIdx.x;
    const int tid  = threadIdx.x;
    const int wid  = tid >> 5;
    const int lane = tid & 31;

    float e[8];
#pragma unroll
    for (int j = 0; j < 8; ++j) e[j] = g_simmax[b * SM_ + tid * 8 + j];

    for (int k = 0; k < NCAND; ++k) {
        float bv = e[0];
        int   bi = tid * 8;
#pragma unroll
        for (int j = 1; j < 8; ++j)
            if (e[j] > bv) { bv = e[j]; bi = tid * 8 + j; }
#pragma unroll
        for (int off = 16; off; off >>= 1) {
            float ov = __shfl_xor_sync(0xffffffffu, bv, off);
            int   oi = __shfl_xor_sync(0xffffffffu, bi, off);
            if (ov > bv || (ov == bv && oi < bi)) { bv = ov; bi = oi; }
        }
        if (lane == 0) { swv[wid] = bv; swi[wid] = bi; }
        __syncthreads();
        if (wid == 0) {
            float fv = (lane < 16) ? swv[lane] : NEG_INF;
            int   fi = (lane < 16) ? swi[lane] : 0x7fffffff;
#pragma unroll
            for (int off = 8; off; off >>= 1) {
                float ov = __shfl_xor_sync(0xffffffffu, fv, off);
                int   oi = __shfl_xor_sync(0xffffffffu, fi, off);
                if (ov > fv || (ov == fv && oi < fi)) { fv = ov; fi = oi; }
            }
            if (lane == 0) {
                s_win = fi;
                g_cand[b * NCAND + k] = fi;
            }
        }
        __syncthreads();
        const int w = s_win;
        if ((w >> 3) == tid) e[w & 7] = NEG_INF;
    }
}

// ---------------------------------------------------------------------------
// 4) exact fp32 re-rank of the 16 candidates (incl. exact candidate norms),
//    pick top-5, gather rows + indices.
//    out layout (float32): 5 blocks of [B,D] then [B,TOPK] indices
// ---------------------------------------------------------------------------
__global__ __launch_bounds__(512)
void rerank_kernel(const float* __restrict__ x, const float* __restrict__ mem,
                   float* __restrict__ out) {
    __shared__ float s_m[NCAND][D];
    __shared__ float s_x[32][D + 1];
    __shared__ float s_invnb[NCAND];
    __shared__ float s_score[NCAND];
    __shared__ int   s_sel[TOPK];

    const int b    = blockIdx.x;
    const int tid  = threadIdx.x;
    const int wid  = tid >> 5;     // 0..15 -> candidate id
    const int lane = tid & 31;

    for (int i = tid; i < NCAND * D; i += 512) {
        int c = i >> 8, d = i & 255;
        s_m[c][d] = mem[((size_t)b * SM_ + g_cand[b * NCAND + c]) * D + d];
    }
    __syncthreads();

    // exact fp32 inverse norm of each candidate (warp wid -> candidate wid)
    {
        float s = 0.0f;
#pragma unroll
        for (int d = lane; d < D; d += 32) s = fmaf(s_m[wid][d], s_m[wid][d], s);
#pragma unroll
        for (int off = 16; off; off >>= 1)
            s += __shfl_xor_sync(0xffffffffu, s, off);
        if (lane == 0) s_invnb[wid] = rsqrtf(s);
    }

    float vmax = NEG_INF;
    for (int s0 = 0; s0 < SX; s0 += 32) {
        __syncthreads();
        for (int i = tid; i < 32 * D; i += 512) {
            int r = i >> 8, d = i & 255;
            s_x[r][d] = x[((size_t)b * SX + s0 + r) * D + d];
        }
        __syncthreads();
        float dot = 0.0f;
#pragma unroll 8
        for (int d = 0; d < D; ++d)
            dot = fmaf(s_x[lane][d], s_m[wid][d], dot);
        vmax = fmaxf(vmax, dot * g_inv_na[b * SX + s0 + lane]);
    }
#pragma unroll
    for (int off = 16; off; off >>= 1)
        vmax = fmaxf(vmax, __shfl_xor_sync(0xffffffffu, vmax, off));
    if (lane == 0)
        s_score[wid] = vmax * s_invnb[wid];
    __syncthreads();

    if (tid == 0) {
        float sc[NCAND];
        int   ix[NCAND];
        for (int i = 0; i < NCAND; ++i) {
            sc[i] = s_score[i];
            ix[i] = g_cand[b * NCAND + i];
        }
        for (int k = 0; k < TOPK; ++k) {
            int best = k;
            for (int j = k + 1; j < NCAND; ++j)
                if (sc[j] > sc[best] || (sc[j] == sc[best] && ix[j] < ix[best])) best = j;
            float ts = sc[k]; sc[k] = sc[best]; sc[best] = ts;
            int   ti = ix[k]; ix[k] = ix[best]; ix[best] = ti;
            s_sel[k] = ix[k];
        }
    }
    __syncthreads();

    if (tid < 256) {
        for (int k = 0; k < TOPK; ++k)
            out[(size_t)k * B * D + (size_t)b * D + tid] =
                mem[((size_t)b * SM_ + s_sel[k]) * D + tid];
    }
    if (tid < TOPK)
        out[(size_t)TOPK * B * D + b * TOPK + tid] = (float)s_sel[tid];
}

// ---------------------------------------------------------------------------
extern "C" void kernel_launch(void* const* d_in, const int* in_sizes, int n_in,
                              void* d_out, int out_size) {
    const float* x   = (const float*)d_in[0];   // [B, SX, D]
    const float* mem = (const float*)d_in[1];   // [B, SM, D]
    float* out = (float*)d_out;
    (void)in_sizes; (void)n_in; (void)out_size;

    invnorm_x_kernel<<<(B * SX) / 8, 256>>>(x);

    const int smem_bytes = (MT * STRIDE + 2 * NC * STRIDE) * 2
                         + (SX + MT + 4 * MT) * 4;               // ~208 KB
    static bool attr_set = false;   // idempotent attribute, not work caching
    if (!attr_set) {
        cudaFuncSetAttribute(simmax_mma_kernel,
                             cudaFuncAttributeMaxDynamicSharedMemorySize, smem_bytes);
        attr_set = true;
    }
    dim3 grid(SM_ / MT, B);
    simmax_mma_kernel<<<grid, NTHREADS, smem_bytes>>>(mem);

    topk_approx_kernel<<<B, 512>>>();
    rerank_kernel<<<B, 512>>>(x, mem, out);
}

// round 11
// speedup vs baseline: 2.4128x; 1.4622x over previous
#include <cuda_runtime.h>
#include <cuda_bf16.h>
#include <cstdint>

// Problem constants
#define B    32
#define SX   512
#define SM_  4096
#define D    256
#define TOPK 5
#define NCAND 16

#define NEG_INF (__int_as_float(0xff800000))

// GEMM tiling
#define MT   128          // mem rows per CTA
#define NC   128          // query chunk
#define NCH  (SX / NC)    // 4 chunks
#define KSTEPS (D / 16)   // 16 k-steps of 16
#define STRIDE 264        // bf16 elems per smem row (528B: 16B aligned, 4-bank stagger)
#define NTHREADS 512

// Scratch (no allocations allowed)
__device__ float g_inv_na[B * SX];
__device__ float g_simmax[B * SM_];
__device__ int   g_cand[B * NCAND];
__device__ float g_score[B * NCAND];
__device__ __nv_bfloat16 g_xbf[B * SX * D];    // 8 MB

// ---------------------------------------------------------------------------
// helpers
// ---------------------------------------------------------------------------
__device__ __forceinline__ uint32_t smem_u32(const void* p) {
    return (uint32_t)__cvta_generic_to_shared(p);
}

__device__ __forceinline__ uint32_t pack_bf2(float a, float b) {
    __nv_bfloat162 h = __float22bfloat162_rn(make_float2(a, b));
    return *reinterpret_cast<uint32_t*>(&h);
}

__device__ __forceinline__ void cp16(uint32_t dst, const void* src) {
    asm volatile("cp.async.cg.shared.global [%0], [%1], 16;" :: "r"(dst), "l"(src));
}
__device__ __forceinline__ void cp_commit() {
    asm volatile("cp.async.commit_group;" ::: "memory");
}
__device__ __forceinline__ void cp_wait0() {
    asm volatile("cp.async.wait_group 0;" ::: "memory");
}

__device__ __forceinline__ void ldsm_x4(uint32_t& r0, uint32_t& r1,
                                        uint32_t& r2, uint32_t& r3, uint32_t addr) {
    asm volatile("ldmatrix.sync.aligned.m8n8.x4.shared.b16 {%0,%1,%2,%3}, [%4];"
                 : "=r"(r0), "=r"(r1), "=r"(r2), "=r"(r3) : "r"(addr));
}

__device__ __forceinline__ void mma_bf16(float& c0, float& c1, float& c2, float& c3,
                                         uint32_t a0, uint32_t a1, uint32_t a2, uint32_t a3,
                                         uint32_t b0, uint32_t b1) {
    asm volatile(
        "mma.sync.aligned.m16n8k16.row.col.f32.bf16.bf16.f32 "
        "{%0,%1,%2,%3}, {%4,%5,%6,%7}, {%8,%9}, {%0,%1,%2,%3};"
        : "+f"(c0), "+f"(c1), "+f"(c2), "+f"(c3)
        : "r"(a0), "r"(a1), "r"(a2), "r"(a3), "r"(b0), "r"(b1));
}

__device__ __forceinline__ float dot8(const float4& a0, const float4& a1,
                                      const float4& b0, const float4& b1) {
    float s = a0.x * b0.x;
    s = fmaf(a0.y, b0.y, s);
    s = fmaf(a0.z, b0.z, s);
    s = fmaf(a0.w, b0.w, s);
    s = fmaf(a1.x, b1.x, s);
    s = fmaf(a1.y, b1.y, s);
    s = fmaf(a1.z, b1.z, s);
    s = fmaf(a1.w, b1.w, s);
    return s;
}

// ---------------------------------------------------------------------------
// 1) x only: inverse L2 norm per row + bf16 conversion (one warp per row)
// ---------------------------------------------------------------------------
__global__ void invnorm_x_kernel(const float* __restrict__ in) {
    int gwarp = (blockIdx.x * blockDim.x + threadIdx.x) >> 5;
    int lane  = threadIdx.x & 31;
    if (gwarp >= B * SX) return;
    const float4* r = reinterpret_cast<const float4*>(in + (size_t)gwarp * D);
    float4 v0 = r[lane];
    float4 v1 = r[lane + 32];

    __nv_bfloat16* dst = g_xbf + (size_t)gwarp * D;
    uint2 wa = make_uint2(pack_bf2(v0.x, v0.y), pack_bf2(v0.z, v0.w));
    uint2 wb = make_uint2(pack_bf2(v1.x, v1.y), pack_bf2(v1.z, v1.w));
    reinterpret_cast<uint64_t*>(dst)[lane]      = *reinterpret_cast<uint64_t*>(&wa);
    reinterpret_cast<uint64_t*>(dst)[lane + 32] = *reinterpret_cast<uint64_t*>(&wb);

    float s = v0.x * v0.x + v0.y * v0.y + v0.z * v0.z + v0.w * v0.w
            + v1.x * v1.x + v1.y * v1.y + v1.z * v1.z + v1.w * v1.w;
#pragma unroll
    for (int off = 16; off; off >>= 1)
        s += __shfl_xor_sync(0xffffffffu, s, off);
    if (lane == 0) g_inv_na[gwarp] = rsqrtf(s);
}

// ---------------------------------------------------------------------------
// 2) fused tensor sim-max (unchanged from R10): A fp32->bf16 in prologue,
//    in-kernel row norms, mma.sync bf16, double-buffered cp.async B chunks.
// ---------------------------------------------------------------------------
__device__ __forceinline__ void load_tile_async(uint32_t sdst,
                                                const __nv_bfloat16* gsrc, int tid) {
#pragma unroll
    for (int i = tid; i < MT * 32; i += NTHREADS) {
        const int r = i >> 5, c = i & 31;
        cp16(sdst + (uint32_t)(r * (STRIDE * 2) + c * 16), gsrc + (size_t)r * D + c * 8);
    }
}

__global__ __launch_bounds__(NTHREADS, 1)
void simmax_mma_kernel(const float* __restrict__ mem) {
    extern __shared__ char smem[];
    __nv_bfloat16* sA  = reinterpret_cast<__nv_bfloat16*>(smem);   // [128][STRIDE]
    __nv_bfloat16* sB0 = sA + MT * STRIDE;
    __nv_bfloat16* sB1 = sB0 + NC * STRIDE;
    float* s_ina = reinterpret_cast<float*>(sB1 + NC * STRIDE);    // [512]
    float* s_inb = s_ina + SX;                                     // [128]
    float* red   = s_inb + MT;                                     // [4*128]

    const int tid    = threadIdx.x;
    const int wid    = tid >> 5;
    const int lane   = tid & 31;
    const int b      = blockIdx.y;
    const int m0     = blockIdx.x * MT;
    const int warp_m = wid & 3;
    const int warp_n = wid >> 2;

    const float* Ag = mem + ((size_t)b * SM_ + m0) * D;
    const __nv_bfloat16* Xg = g_xbf + (size_t)b * SX * D;

    load_tile_async(smem_u32(sB0), Xg, tid);
    cp_commit();

    // A tile: fp32 LDG -> bf16 STS. 128 rows x 64 float4 = 8192 ops.
#pragma unroll
    for (int j = 0; j < 16; ++j) {
        const int idx = j * NTHREADS + tid;
        const int r = idx >> 6, q = idx & 63;
        float4 v = reinterpret_cast<const float4*>(Ag)[(size_t)r * 64 + q];
        uint2 w = make_uint2(pack_bf2(v.x, v.y), pack_bf2(v.z, v.w));
        *reinterpret_cast<uint2*>(
            reinterpret_cast<char*>(sA) + r * (STRIDE * 2) + q * 8) = w;
    }
#pragma unroll
    for (int i = tid; i < SX; i += NTHREADS) s_ina[i] = g_inv_na[b * SX + i];
    __syncthreads();

    // per-row inv norms from the bf16 A tile: 4 threads per row
    {
        const int r  = tid >> 2;
        const int q0 = (tid & 3) * 64;
        const __nv_bfloat16* row = sA + r * STRIDE + q0;
        float s = 0.0f;
#pragma unroll
        for (int k = 0; k < 32; ++k) {
            float2 p = __bfloat1622float2(
                *reinterpret_cast<const __nv_bfloat162*>(row + 2 * k));
            s = fmaf(p.x, p.x, fmaf(p.y, p.y, s));
        }
        s += __shfl_xor_sync(0xffffffffu, s, 1);
        s += __shfl_xor_sync(0xffffffffu, s, 2);
        if ((tid & 3) == 0) s_inb[r] = rsqrtf(s);
    }
    cp_wait0();
    __syncthreads();

    const int g = lane >> 3, r8 = lane & 7;
    const uint32_t aA = smem_u32(sA) +
        (uint32_t)(((warp_m * 32 + (g & 1) * 8 + r8) * STRIDE + (g >> 1) * 8) * 2);
    const uint32_t aBoff =
        (uint32_t)(((warp_n * 32 + (g >> 1) * 8 + r8) * STRIDE + (g & 1) * 8) * 2);
    const uint32_t aBbuf[2] = { smem_u32(sB0) + aBoff, smem_u32(sB1) + aBoff };
    const uint32_t sBbuf[2] = { smem_u32(sB0), smem_u32(sB1) };

    float rmax[2][2];
#pragma unroll
    for (int i = 0; i < 2; ++i) rmax[i][0] = rmax[i][1] = NEG_INF;

    for (int c = 0; c < NCH; ++c) {
        if (c + 1 < NCH) {
            load_tile_async(sBbuf[(c + 1) & 1], Xg + (size_t)(c + 1) * NC * D, tid);
            cp_commit();
        }

        const uint32_t aB = aBbuf[c & 1];
        float acc[2][4][4];
#pragma unroll
        for (int mt = 0; mt < 2; ++mt)
#pragma unroll
            for (int nt = 0; nt < 4; ++nt)
#pragma unroll
                for (int q = 0; q < 4; ++q) acc[mt][nt][q] = 0.0f;

#pragma unroll 4
        for (int ks = 0; ks < KSTEPS; ++ks) {
            const uint32_t koff = (uint32_t)(ks * 16 * 2);
            uint32_t a[2][4];
#pragma unroll
            for (int mt = 0; mt < 2; ++mt)
                ldsm_x4(a[mt][0], a[mt][1], a[mt][2], a[mt][3],
                        aA + (uint32_t)(mt * 16 * STRIDE * 2) + koff);
            uint32_t bfr[4][2];
#pragma unroll
            for (int p = 0; p < 2; ++p) {
                uint32_t r0, r1, r2, r3;
                ldsm_x4(r0, r1, r2, r3,
                        aB + (uint32_t)(p * 16 * STRIDE * 2) + koff);
                bfr[p * 2][0]     = r0; bfr[p * 2][1]     = r1;
                bfr[p * 2 + 1][0] = r2; bfr[p * 2 + 1][1] = r3;
            }
#pragma unroll
            for (int mt = 0; mt < 2; ++mt)
#pragma unroll
                for (int nt = 0; nt < 4; ++nt)
                    mma_bf16(acc[mt][nt][0], acc[mt][nt][1],
                             acc[mt][nt][2], acc[mt][nt][3],
                             a[mt][0], a[mt][1], a[mt][2], a[mt][3],
                             bfr[nt][0], bfr[nt][1]);
        }

#pragma unroll
        for (int nt = 0; nt < 4; ++nt) {
            const int n0 = c * NC + warp_n * 32 + nt * 8 + (lane & 3) * 2;
            const float i0 = s_ina[n0], i1 = s_ina[n0 + 1];
#pragma unroll
            for (int mt = 0; mt < 2; ++mt) {
                rmax[mt][0] = fmaxf(rmax[mt][0],
                                    fmaxf(acc[mt][nt][0] * i0, acc[mt][nt][1] * i1));
                rmax[mt][1] = fmaxf(rmax[mt][1],
                                    fmaxf(acc[mt][nt][2] * i0, acc[mt][nt][3] * i1));
            }
        }

        if (c + 1 < NCH) {
            cp_wait0();
            __syncthreads();
        }
    }

#pragma unroll
    for (int mt = 0; mt < 2; ++mt)
#pragma unroll
        for (int rh = 0; rh < 2; ++rh) {
            float v = rmax[mt][rh];
            v = fmaxf(v, __shfl_xor_sync(0xffffffffu, v, 1));
            v = fmaxf(v, __shfl_xor_sync(0xffffffffu, v, 2));
            rmax[mt][rh] = v;
        }
    __syncthreads();
    if ((lane & 3) == 0) {
#pragma unroll
        for (int mt = 0; mt < 2; ++mt)
#pragma unroll
            for (int rh = 0; rh < 2; ++rh) {
                const int m = warp_m * 32 + mt * 16 + rh * 8 + (lane >> 2);
                red[warp_n * MT + m] = rmax[mt][rh];
            }
    }
    __syncthreads();
    if (tid < MT) {
        float v = fmaxf(fmaxf(red[tid], red[MT + tid]),
                        fmaxf(red[2 * MT + tid], red[3 * MT + tid]));
        g_simmax[b * SM_ + m0 + tid] = v * s_inb[tid];
    }
}

// ---------------------------------------------------------------------------
// 3) approx top-16 per batch: register-resident, warp-shuffle argmax rounds
// ---------------------------------------------------------------------------
__global__ __launch_bounds__(512)
void topk_approx_kernel() {
    __shared__ float swv[16];
    __shared__ int   swi[16];
    __shared__ int   s_win;

    const int b    = blockIdx.x;
    const int tid  = threadIdx.x;
    const int wid  = tid >> 5;
    const int lane = tid & 31;

    float e[8];
#pragma unroll
    for (int j = 0; j < 8; ++j) e[j] = g_simmax[b * SM_ + tid * 8 + j];

    for (int k = 0; k < NCAND; ++k) {
        float bv = e[0];
        int   bi = tid * 8;
#pragma unroll
        for (int j = 1; j < 8; ++j)
            if (e[j] > bv) { bv = e[j]; bi = tid * 8 + j; }
#pragma unroll
        for (int off = 16; off; off >>= 1) {
            float ov = __shfl_xor_sync(0xffffffffu, bv, off);
            int   oi = __shfl_xor_sync(0xffffffffu, bi, off);
            if (ov > bv || (ov == bv && oi < bi)) { bv = ov; bi = oi; }
        }
        if (lane == 0) { swv[wid] = bv; swi[wid] = bi; }
        __syncthreads();
        if (wid == 0) {
            float fv = (lane < 16) ? swv[lane] : NEG_INF;
            int   fi = (lane < 16) ? swi[lane] : 0x7fffffff;
#pragma unroll
            for (int off = 8; off; off >>= 1) {
                float ov = __shfl_xor_sync(0xffffffffu, fv, off);
                int   oi = __shfl_xor_sync(0xffffffffu, fi, off);
                if (ov > fv || (ov == fv && oi < fi)) { fv = ov; fi = oi; }
            }
            if (lane == 0) {
                s_win = fi;
                g_cand[b * NCAND + k] = fi;
            }
        }
        __syncthreads();
        const int w = s_win;
        if ((w >> 3) == tid) e[w & 7] = NEG_INF;
    }
}

// ---------------------------------------------------------------------------
// 4) exact fp32 scores for candidate PAIRS: grid (B, NCAND/2), 512 threads.
//    Candidate rows in registers; each warp owns 32 queries; butterfly dots.
// ---------------------------------------------------------------------------
__global__ __launch_bounds__(512)
void rerank_score_kernel(const float* __restrict__ x, const float* __restrict__ mem) {
    __shared__ float s_wmax[16][2];
    __shared__ float s_invnb[2];

    const int b    = blockIdx.x;
    const int c0   = blockIdx.y * 2;
    const int tid  = threadIdx.x;
    const int wid  = tid >> 5;
    const int lane = tid & 31;

    const int i0 = g_cand[b * NCAND + c0];
    const int i1 = g_cand[b * NCAND + c0 + 1];
    const float4* M0 = reinterpret_cast<const float4*>(mem + ((size_t)b * SM_ + i0) * D);
    const float4* M1 = reinterpret_cast<const float4*>(mem + ((size_t)b * SM_ + i1) * D);
    const float4 m0a = M0[lane], m0b = M0[lane + 32];
    const float4 m1a = M1[lane], m1b = M1[lane + 32];

    // exact fp32 inverse norms (warps 0 and 1)
    if (wid < 2) {
        float s = wid ? dot8(m1a, m1b, m1a, m1b) : dot8(m0a, m0b, m0a, m0b);
#pragma unroll
        for (int off = 16; off; off >>= 1)
            s += __shfl_xor_sync(0xffffffffu, s, off);
        if (lane == 0) s_invnb[wid] = rsqrtf(s);
    }

    const float* Xb = x + (size_t)b * SX * D;
    float v0 = NEG_INF, v1 = NEG_INF;
#pragma unroll 4
    for (int i = 0; i < SX / 16; ++i) {
        const int s = wid + 16 * i;
        const float4* X = reinterpret_cast<const float4*>(Xb + (size_t)s * D);
        const float4 xa = X[lane], xb = X[lane + 32];
        float d0 = dot8(m0a, m0b, xa, xb);
        float d1 = dot8(m1a, m1b, xa, xb);
#pragma unroll
        for (int off = 16; off; off >>= 1) {
            d0 += __shfl_xor_sync(0xffffffffu, d0, off);
            d1 += __shfl_xor_sync(0xffffffffu, d1, off);
        }
        const float ina = g_inv_na[b * SX + s];
        v0 = fmaxf(v0, d0 * ina);
        v1 = fmaxf(v1, d1 * ina);
    }
    if (lane == 0) { s_wmax[wid][0] = v0; s_wmax[wid][1] = v1; }
    __syncthreads();
    if (tid < 2) {
        float m = NEG_INF;
#pragma unroll
        for (int j = 0; j < 16; ++j) m = fmaxf(m, s_wmax[j][tid]);
        g_score[b * NCAND + c0 + tid] = m * s_invnb[tid];
    }
}

// ---------------------------------------------------------------------------
// 5) pick top-5 of the 16 exact scores, gather rows + indices.
//    out layout (float32): 5 blocks of [B,D] then [B,TOPK] indices
// ---------------------------------------------------------------------------
__global__ __launch_bounds__(256)
void select_gather_kernel(const float* __restrict__ mem, float* __restrict__ out) {
    __shared__ int s_sel[TOPK];
    const int b   = blockIdx.x;
    const int tid = threadIdx.x;

    if (tid == 0) {
        float sc[NCAND];
        int   ix[NCAND];
        for (int i = 0; i < NCAND; ++i) {
            sc[i] = g_score[b * NCAND + i];
            ix[i] = g_cand[b * NCAND + i];
        }
        for (int k = 0; k < TOPK; ++k) {
            int best = k;
            for (int j = k + 1; j < NCAND; ++j)
                if (sc[j] > sc[best] || (sc[j] == sc[best] && ix[j] < ix[best])) best = j;
            float ts = sc[k]; sc[k] = sc[best]; sc[best] = ts;
            int   ti = ix[k]; ix[k] = ix[best]; ix[best] = ti;
            s_sel[k] = ix[k];
        }
    }
    __syncthreads();

#pragma unroll
    for (int k = 0; k < TOPK; ++k)
        out[(size_t)k * B * D + (size_t)b * D + tid] =
            mem[((size_t)b * SM_ + s_sel[k]) * D + tid];
    if (tid < TOPK)
        out[(size_t)TOPK * B * D + b * TOPK + tid] = (float)s_sel[tid];
}

// ---------------------------------------------------------------------------
extern "C" void kernel_launch(void* const* d_in, const int* in_sizes, int n_in,
                              void* d_out, int out_size) {
    const float* x   = (const float*)d_in[0];   // [B, SX, D]
    const float* mem = (const float*)d_in[1];   // [B, SM, D]
    float* out = (float*)d_out;
    (void)in_sizes; (void)n_in; (void)out_size;

    invnorm_x_kernel<<<(B * SX) / 8, 256>>>(x);

    const int smem_bytes = (MT * STRIDE + 2 * NC * STRIDE) * 2
                         + (SX + MT + 4 * MT) * 4;               // ~208 KB
    static bool attr_set = false;   // idempotent attribute, not work caching
    if (!attr_set) {
        cudaFuncSetAttribute(simmax_mma_kernel,
                             cudaFuncAttributeMaxDynamicSharedMemorySize, smem_bytes);
        attr_set = true;
    }
    dim3 grid(SM_ / MT, B);
    simmax_mma_kernel<<<grid, NTHREADS, smem_bytes>>>(mem);

    topk_approx_kernel<<<B, 512>>>();
    rerank_score_kernel<<<dim3(B, NCAND / 2), 512>>>(x, mem);
    select_gather_kernel<<<B, 256>>>(mem, out);
}